// round 13
// baseline (speedup 1.0000x reference)
#include <cuda_runtime.h>
#include <cuda_bf16.h>
#include <math.h>

// Scratch: exact integer histograms for the two tensors (no allocation allowed).
__device__ unsigned int g_hist[2][256];

__global__ void zero_hist_kernel() {
    int t = threadIdx.x;
    if (t < 256) {
        g_hist[0][t] = 0u;
        g_hist[1][t] = 0u;
    }
}

// Per-warp privatized shared-memory histogram (bit-exact binning, proven).
__global__ __launch_bounds__(256) void hist_kernel(
    const float* __restrict__ pred,
    const float* __restrict__ gt,
    int n4)
{
    __shared__ unsigned int sh[8][256];

    const float4* __restrict__ src =
        (blockIdx.y == 0) ? (const float4*)pred : (const float4*)gt;

    #pragma unroll
    for (int i = threadIdx.x; i < 8 * 256; i += 256)
        ((unsigned int*)sh)[i] = 0u;
    __syncthreads();

    const int warp = threadIdx.x >> 5;
    unsigned int* __restrict__ h = sh[warp];

    const int stride = gridDim.x * blockDim.x;
    for (int i = blockIdx.x * blockDim.x + threadIdx.x; i < n4; i += stride) {
        float4 v = src[i];
        {
            float s = __fadd_rn(v.x, 1.0f);
            float t = __fmul_rn(s, 128.0f);
            int b = min(max(__float2int_rd(t), 0), 255);
            if (v.x >= -1.0f && v.x <= 1.0f) atomicAdd(&h[b], 1u);
        }
        {
            float s = __fadd_rn(v.y, 1.0f);
            float t = __fmul_rn(s, 128.0f);
            int b = min(max(__float2int_rd(t), 0), 255);
            if (v.y >= -1.0f && v.y <= 1.0f) atomicAdd(&h[b], 1u);
        }
        {
            float s = __fadd_rn(v.z, 1.0f);
            float t = __fmul_rn(s, 128.0f);
            int b = min(max(__float2int_rd(t), 0), 255);
            if (v.z >= -1.0f && v.z <= 1.0f) atomicAdd(&h[b], 1u);
        }
        {
            float s = __fadd_rn(v.w, 1.0f);
            float t = __fmul_rn(s, 128.0f);
            int b = min(max(__float2int_rd(t), 0), 255);
            if (v.w >= -1.0f && v.w <= 1.0f) atomicAdd(&h[b], 1u);
        }
    }
    __syncthreads();

    for (int bin = threadIdx.x; bin < 256; bin += 256) {
        unsigned int s = 0;
        #pragma unroll
        for (int w = 0; w < 8; w++) s += sh[w][bin];
        if (s) atomicAdd(&g_hist[blockIdx.y][bin], s);
    }
}

// XLA-CPU's vectorized f32 log (Cephes / sse_mathfun port, as in
// llvm_ir_runtime's LogV4F32), with AArch64 FMA contraction applied wherever
// a mul feeds an add (fmla/fmls). Valid for positive normal inputs (ours are
// in (1e-8, 0.03]).
__device__ __forceinline__ float cephes_logf_fma(float xin) {
    unsigned ux = __float_as_uint(xin);
    float e = (float)((int)(ux >> 23) - 126);           // exponent, m in [0.5,1)
    float m = __uint_as_float((ux & 0x007fffffu) | 0x3f000000u);
    float x;
    if (m < 0.707106781186547524f) {
        e = __fadd_rn(e, -1.0f);
        x = __fadd_rn(__fadd_rn(m, -1.0f), m);          // (m-1)+m, both exact
    } else {
        x = __fadd_rn(m, -1.0f);                        // exact (Sterbenz)
    }
    float z = __fmul_rn(x, x);
    float y = 7.0376836292e-2f;
    y = fmaf(y, x, -1.1514610310e-1f);
    y = fmaf(y, x,  1.1676998740e-1f);
    y = fmaf(y, x, -1.2420140846e-1f);
    y = fmaf(y, x,  1.4249322787e-1f);
    y = fmaf(y, x, -1.6668057665e-1f);
    y = fmaf(y, x,  2.0000714765e-1f);
    y = fmaf(y, x, -2.4999993993e-1f);
    y = fmaf(y, x,  3.3333331174e-1f);
    y = __fmul_rn(y, x);
    y = __fmul_rn(y, z);
    y = fmaf(e, -2.12194440e-4f, y);                    // y += e*q1   (fmla)
    y = fmaf(-0.5f, z, y);                              // y -= 0.5*z  (fmls)
    float r = __fadd_rn(x, y);
    r = fmaf(e, 0.693359375f, r);                       // r += e*q2   (fmla)
    return r;
}

// Single thread replays the XLA-CPU (fast-math, NEON) entropy pipeline:
//  T: vectorized sum == RNE(exact integer total)  [proven order-invariant]
//  S: loop vectorized at VF=4, IC=1 -> 4 stride-4 accumulators, and the
//     reduction add CONTRACTS with the term mul: acc = fma(p, log p, acc).
//     Horizontal faddp finish: (a0+a1) + (a2+a3).
//  div: IEEE div.rn; eps-add plain (no mul feeds it); log = Cephes-fma.
__global__ void entropy_kernel(float* __restrict__ out) {
    if (threadIdx.x != 0 || blockIdx.x != 0) return;

    float H[2];
    for (int j = 0; j < 2; j++) {
        unsigned long long tot = 0;
        for (int b = 0; b < 256; b++) tot += (unsigned long long)g_hist[j][b];
        float T = (float)tot;   // RNE of exact total

        float a0 = 0.0f, a1 = 0.0f, a2 = 0.0f, a3 = 0.0f;
        for (int k = 0; k < 64; k++) {
            #pragma unroll
            for (int j2 = 0; j2 < 4; j2++) {
                int b = 4 * k + j2;
                float c  = (float)g_hist[j][b];                // exact
                float p  = __fadd_rn(__fdiv_rn(c, T), 1e-8f);
                float lg = cephes_logf_fma(p);
                float* acc = (j2 == 0) ? &a0 : (j2 == 1) ? &a1 : (j2 == 2) ? &a2 : &a3;
                *acc = fmaf(p, lg, *acc);                      // fmla accumulate
            }
        }
        float S = __fadd_rn(__fadd_rn(a0, a1), __fadd_rn(a2, a3));
        H[j] = -S;
    }
    out[0] = fabsf(__fadd_rn(H[0], -H[1]));
}

extern "C" void kernel_launch(void* const* d_in, const int* in_sizes, int n_in,
                              void* d_out, int out_size) {
    const float* pred = (const float*)d_in[0];
    const float* gt   = (const float*)d_in[1];
    float* out = (float*)d_out;

    int n = in_sizes[0];          // 33,554,432 per tensor
    int n4 = n >> 2;

    zero_hist_kernel<<<1, 256>>>();

    dim3 grid(592, 2);
    hist_kernel<<<grid, 256>>>(pred, gt, n4);

    entropy_kernel<<<1, 32>>>(out);
}

// round 15
// speedup vs baseline: 1.7374x; 1.7374x over previous
#include <cuda_runtime.h>
#include <cuda_bf16.h>
#include <math.h>

// Scratch histograms. Device globals are zero-initialized at module load;
// entropy_kernel re-zeroes them after consuming, so every call (and every
// graph replay) starts from zero. No separate zeroing launch needed.
__device__ unsigned int g_hist[2][256];

// Per-warp privatized shared-memory histogram (bit-exact binning, proven).
__global__ __launch_bounds__(256) void hist_kernel(
    const float* __restrict__ pred,
    const float* __restrict__ gt,
    int n4)
{
    __shared__ unsigned int sh[8][256];

    const float4* __restrict__ src =
        (blockIdx.y == 0) ? (const float4*)pred : (const float4*)gt;

    #pragma unroll
    for (int i = threadIdx.x; i < 8 * 256; i += 256)
        ((unsigned int*)sh)[i] = 0u;
    __syncthreads();

    const int warp = threadIdx.x >> 5;
    unsigned int* __restrict__ h = sh[warp];

    const int stride = gridDim.x * blockDim.x;
    for (int i = blockIdx.x * blockDim.x + threadIdx.x; i < n4; i += stride) {
        float4 v = src[i];
        {
            float s = __fadd_rn(v.x, 1.0f);
            float t = __fmul_rn(s, 128.0f);
            int b = min(max(__float2int_rd(t), 0), 255);
            if (v.x >= -1.0f && v.x <= 1.0f) atomicAdd(&h[b], 1u);
        }
        {
            float s = __fadd_rn(v.y, 1.0f);
            float t = __fmul_rn(s, 128.0f);
            int b = min(max(__float2int_rd(t), 0), 255);
            if (v.y >= -1.0f && v.y <= 1.0f) atomicAdd(&h[b], 1u);
        }
        {
            float s = __fadd_rn(v.z, 1.0f);
            float t = __fmul_rn(s, 128.0f);
            int b = min(max(__float2int_rd(t), 0), 255);
            if (v.z >= -1.0f && v.z <= 1.0f) atomicAdd(&h[b], 1u);
        }
        {
            float s = __fadd_rn(v.w, 1.0f);
            float t = __fmul_rn(s, 128.0f);
            int b = min(max(__float2int_rd(t), 0), 255);
            if (v.w >= -1.0f && v.w <= 1.0f) atomicAdd(&h[b], 1u);
        }
    }
    __syncthreads();

    for (int bin = threadIdx.x; bin < 256; bin += 256) {
        unsigned int s = 0;
        #pragma unroll
        for (int w = 0; w < 8; w++) s += sh[w][bin];
        if (s) atomicAdd(&g_hist[blockIdx.y][bin], s);
    }
}

// XLA-CPU's vectorized f32 log (Cephes / sse_mathfun) with AArch64 FMA
// contraction wherever a mul feeds an add (fmla/fmls). Verified bit-exact
// against the reference in R13.
__device__ __forceinline__ float cephes_logf_fma(float xin) {
    unsigned ux = __float_as_uint(xin);
    float e = (float)((int)(ux >> 23) - 126);           // exponent, m in [0.5,1)
    float m = __uint_as_float((ux & 0x007fffffu) | 0x3f000000u);
    float x;
    if (m < 0.707106781186547524f) {
        e = __fadd_rn(e, -1.0f);
        x = __fadd_rn(__fadd_rn(m, -1.0f), m);
    } else {
        x = __fadd_rn(m, -1.0f);
    }
    float z = __fmul_rn(x, x);
    float y = 7.0376836292e-2f;
    y = fmaf(y, x, -1.1514610310e-1f);
    y = fmaf(y, x,  1.1676998740e-1f);
    y = fmaf(y, x, -1.2420140846e-1f);
    y = fmaf(y, x,  1.4249322787e-1f);
    y = fmaf(y, x, -1.6668057665e-1f);
    y = fmaf(y, x,  2.0000714765e-1f);
    y = fmaf(y, x, -2.4999993993e-1f);
    y = fmaf(y, x,  3.3333331174e-1f);
    y = __fmul_rn(y, x);
    y = __fmul_rn(y, z);
    y = fmaf(e, -2.12194440e-4f, y);
    y = fmaf(-0.5f, z, y);
    float r = __fadd_rn(x, y);
    r = fmaf(e, 0.693359375f, r);
    return r;
}

// Entropy epilogue, parallelized but bit-identical to the R13-passing serial
// version: 256 threads compute (p, log p) per bin; thread 0 then replays the
// exact VF4/IC1 fused-accumulate chain over the precomputed values (same
// values, same order -> same bits). Also re-zeroes g_hist for the next call.
__global__ __launch_bounds__(256) void entropy_kernel(float* __restrict__ out) {
    __shared__ float sp[2][256];
    __shared__ float sl[2][256];
    __shared__ unsigned long long stot[2][8];

    const int t = threadIdx.x;
    const int warp = t >> 5, lane = t & 31;

    unsigned int c0 = g_hist[0][t];
    unsigned int c1 = g_hist[1][t];

    // Exact integer totals via warp + cross-warp reduce (order-free).
    unsigned long long u0 = c0, u1 = c1;
    #pragma unroll
    for (int off = 16; off >= 1; off >>= 1) {
        u0 += __shfl_down_sync(0xffffffffu, u0, off);
        u1 += __shfl_down_sync(0xffffffffu, u1, off);
    }
    if (lane == 0) { stot[0][warp] = u0; stot[1][warp] = u1; }
    __syncthreads();

    unsigned long long tot0 = 0, tot1 = 0;
    #pragma unroll
    for (int w = 0; w < 8; w++) { tot0 += stot[0][w]; tot1 += stot[1][w]; }
    float T0 = (float)tot0;   // RNE of exact total
    float T1 = (float)tot1;

    // Per-bin p and log p (identical arithmetic to the serial version).
    {
        float p  = __fadd_rn(__fdiv_rn((float)c0, T0), 1e-8f);
        sp[0][t] = p;  sl[0][t] = cephes_logf_fma(p);
    }
    {
        float p  = __fadd_rn(__fdiv_rn((float)c1, T1), 1e-8f);
        sp[1][t] = p;  sl[1][t] = cephes_logf_fma(p);
    }

    // Re-zero scratch for the next call (after all reads above).
    g_hist[0][t] = 0u;
    g_hist[1][t] = 0u;
    __syncthreads();

    if (t == 0) {
        float H[2];
        #pragma unroll
        for (int j = 0; j < 2; j++) {
            float a0 = 0.0f, a1 = 0.0f, a2 = 0.0f, a3 = 0.0f;
            for (int k = 0; k < 64; k++) {
                a0 = fmaf(sp[j][4 * k + 0], sl[j][4 * k + 0], a0);
                a1 = fmaf(sp[j][4 * k + 1], sl[j][4 * k + 1], a1);
                a2 = fmaf(sp[j][4 * k + 2], sl[j][4 * k + 2], a2);
                a3 = fmaf(sp[j][4 * k + 3], sl[j][4 * k + 3], a3);
            }
            float S = __fadd_rn(__fadd_rn(a0, a1), __fadd_rn(a2, a3));
            H[j] = -S;
        }
        out[0] = fabsf(__fadd_rn(H[0], -H[1]));
    }
}

extern "C" void kernel_launch(void* const* d_in, const int* in_sizes, int n_in,
                              void* d_out, int out_size) {
    const float* pred = (const float*)d_in[0];
    const float* gt   = (const float*)d_in[1];
    float* out = (float*)d_out;

    int n = in_sizes[0];          // 33,554,432 per tensor
    int n4 = n >> 2;

    dim3 grid(592, 2);
    hist_kernel<<<grid, 256>>>(pred, gt, n4);

    entropy_kernel<<<1, 256>>>(out);
}